// round 3
// baseline (speedup 1.0000x reference)
#include <cuda_runtime.h>
#include <cuda_bf16.h>

#define DNF  133
#define DPAD 136   // padded stride: 544 B rows, 16B-aligned for float4
#define MAXN 50000
#define MAXE 800000
#define NGRAPH 256

// ---------------- static device scratch (zero-initialized at load) ----------------
__device__ float g_hp[MAXN * DPAD];    // (X@W) * dinv[row], cols 133..135 stay 0
__device__ float g_feat[MAXN * DPAD];  // layer outputs, cols 133..135 stay 0
__device__ int   g_deg[MAXN];
__device__ float g_dinv[MAXN];
__device__ int   g_rowptr[MAXN + 1];
__device__ int   g_pos[MAXN];
__device__ int   g_col[MAXE];
__device__ int   g_is64;               // 1 if edge_index/batch are int64, else int32

// ---------------- dtype detection ----------------
// If data is int64 with values < 2^31, every odd int32 word is 0.
// If data is int32 (random node ids), odd words are almost surely nonzero.
__global__ void detect_kernel(const int* __restrict__ w) {
    if (threadIdx.x == 0 && blockIdx.x == 0) {
        int ok = 1;
        for (int i = 1; i < 2048; i += 2)
            if (w[i] != 0) { ok = 0; break; }
        g_is64 = ok;
    }
}

__device__ __forceinline__ int load_idx(const void* p, long long i) {
    return g_is64 ? (int)((const long long*)p)[i] : ((const int*)p)[i];
}

// ---------------- degree / normalization ----------------
__global__ void init_deg_kernel(int n) {
    int i = blockIdx.x * blockDim.x + threadIdx.x;
    if (i < n) g_deg[i] = 1;  // self-loop
}

__global__ void count_deg_kernel(const void* __restrict__ ei, int e) {
    int i = blockIdx.x * blockDim.x + threadIdx.x;
    if (i < e) {
        int d = load_idx(ei, (long long)e + i);  // dst = second row
        atomicAdd(&g_deg[d], 1);
    }
}

__global__ void dinv_kernel(int n) {
    int i = blockIdx.x * blockDim.x + threadIdx.x;
    if (i < n) g_dinv[i] = rsqrtf((float)g_deg[i]);
}

// Exclusive scan of (deg-1) into rowptr. Single block.
__global__ void scan_kernel(int n) {
    __shared__ int psum[512];
    __shared__ int total_s;
    int t = threadIdx.x;
    int chunk = (n + 511) / 512;
    int begin = t * chunk;
    int end = begin + chunk; if (end > n) end = n;
    int s = 0;
    for (int i = begin; i < end; i++) s += g_deg[i] - 1;
    psum[t] = s;
    __syncthreads();
    if (t == 0) {
        int running = 0;
        for (int i = 0; i < 512; i++) { int v = psum[i]; psum[i] = running; running += v; }
        total_s = running;
    }
    __syncthreads();
    int run = psum[t];
    for (int i = begin; i < end; i++) { g_rowptr[i] = run; run += g_deg[i] - 1; }
    if (t == 0) g_rowptr[n] = total_s;
}

__global__ void copy_pos_kernel(int n) {
    int i = blockIdx.x * blockDim.x + threadIdx.x;
    if (i < n) g_pos[i] = g_rowptr[i];
}

__global__ void fill_kernel(const void* __restrict__ ei, int e) {
    int i = blockIdx.x * blockDim.x + threadIdx.x;
    if (i < e) {
        int sidx = load_idx(ei, i);
        int d    = load_idx(ei, (long long)e + i);
        int p = atomicAdd(&g_pos[d], 1);
        g_col[p] = sidx;
    }
}

// ---------------- GEMM: g_hp[r][c] = dinv[r] * sum_k X[r][k]*W[k][c] ----------------
// 256 threads/block, 64 rows x 133 cols; K tiled by 32 (static smem < 48KB).
__global__ void gemm_scale_kernel(const float* __restrict__ Xext,
                                  const float* __restrict__ W,
                                  int use_ext, int n) {
    __shared__ float Ws[32][DNF + 3];
    __shared__ float Xs[64][33];

    const float* X = use_ext ? Xext : (const float*)g_feat;
    int ldx = use_ext ? DNF : DPAD;
    int tid = threadIdx.x;
    int lane = tid & 31, warp = tid >> 5;
    int row0 = blockIdx.x * 64;
    int rbase = warp * 8;

    float acc[8][5];
#pragma unroll
    for (int i = 0; i < 8; i++)
#pragma unroll
        for (int j = 0; j < 5; j++) acc[i][j] = 0.f;

    for (int k0 = 0; k0 < DNF; k0 += 32) {
        int kc = DNF - k0; if (kc > 32) kc = 32;

        for (int i = tid; i < kc * DNF; i += 256) {
            int kk = i / DNF, c = i - kk * DNF;
            Ws[kk][c] = W[(k0 + kk) * DNF + c];
        }
        for (int i = tid; i < 64 * 32; i += 256) {
            int r = i >> 5, kk = i & 31;
            int gr = row0 + r;
            Xs[r][kk] = (kk < kc && gr < n) ? X[(size_t)gr * ldx + k0 + kk] : 0.f;
        }
        __syncthreads();

        for (int kk = 0; kk < kc; kk++) {
            float b[5];
#pragma unroll
            for (int j = 0; j < 4; j++) b[j] = Ws[kk][lane + 32 * j];
            b[4] = (lane < DNF - 128) ? Ws[kk][lane + 128] : 0.f;
#pragma unroll
            for (int i = 0; i < 8; i++) {
                float a = Xs[rbase + i][kk];
#pragma unroll
                for (int j = 0; j < 5; j++) acc[i][j] += a * b[j];
            }
        }
        __syncthreads();
    }

#pragma unroll
    for (int i = 0; i < 8; i++) {
        int r = row0 + rbase + i;
        if (r < n) {
            float di = g_dinv[r];
#pragma unroll
            for (int j = 0; j < 5; j++) {
                int c = lane + 32 * j;
                if (c < DNF) g_hp[(size_t)r * DPAD + c] = acc[i][j] * di;
            }
        }
    }
}

// ---------------- aggregate: g_feat[i] = relu(dinv[i]*(sum_in hp[j] + hp[i]) + bias) ----------------
// One warp per node. float4 per lane covers cols 0..127; lanes 0..4 handle 128..132.
__global__ void aggregate_kernel(const float* __restrict__ bias, int n) {
    int node = blockIdx.x * (blockDim.x >> 5) + (threadIdx.x >> 5);
    if (node >= n) return;
    int lane = threadIdx.x & 31;

    const float4* self4 = (const float4*)(g_hp + (size_t)node * DPAD);
    float4 acc4 = self4[lane];
    float accs = (lane < 5) ? g_hp[(size_t)node * DPAD + 128 + lane] : 0.f;

    int s = g_rowptr[node], e = g_rowptr[node + 1];
    for (int idx = s; idx < e; idx++) {
        int jn = g_col[idx];
        const float4* row4 = (const float4*)(g_hp + (size_t)jn * DPAD);
        float4 v = row4[lane];
        acc4.x += v.x; acc4.y += v.y; acc4.z += v.z; acc4.w += v.w;
        if (lane < 5) accs += g_hp[(size_t)jn * DPAD + 128 + lane];
    }

    float di = g_dinv[node];
    float b0 = bias[4 * lane + 0], b1 = bias[4 * lane + 1];
    float b2 = bias[4 * lane + 2], b3 = bias[4 * lane + 3];
    float4 o;
    o.x = fmaxf(fmaf(acc4.x, di, b0), 0.f);
    o.y = fmaxf(fmaf(acc4.y, di, b1), 0.f);
    o.z = fmaxf(fmaf(acc4.z, di, b2), 0.f);
    o.w = fmaxf(fmaf(acc4.w, di, b3), 0.f);
    ((float4*)(g_feat + (size_t)node * DPAD))[lane] = o;
    if (lane < 5)
        g_feat[(size_t)node * DPAD + 128 + lane] =
            fmaxf(fmaf(accs, di, bias[128 + lane]), 0.f);
}

// ---------------- global mean pool ----------------
__device__ __forceinline__ int lbound_any(const void* a, int n, int v) {
    int lo = 0, hi = n;
    while (lo < hi) {
        int m = (lo + hi) >> 1;
        long long x = g_is64 ? ((const long long*)a)[m]
                             : (long long)((const int*)a)[m];
        if (x < (long long)v) lo = m + 1; else hi = m;
    }
    return lo;
}

__global__ void pool_kernel(const void* __restrict__ batch,
                            float* __restrict__ out, int n) {
    __shared__ int lo_s, hi_s;
    int g = blockIdx.x;
    if (threadIdx.x == 0) {
        lo_s = lbound_any(batch, n, g);
        hi_s = lbound_any(batch, n, g + 1);
    }
    __syncthreads();
    int lo = lo_s, hi = hi_s;
    int c = threadIdx.x;
    if (c < DNF) {
        float s = 0.f;
        for (int r = lo; r < hi; r++) s += g_feat[(size_t)r * DPAD + c];
        int cnt = hi - lo;
        out[g * DNF + c] = s / (float)(cnt > 0 ? cnt : 1);
    }
}

// ---------------- launch: kernel launches ONLY ----------------
extern "C" void kernel_launch(void* const* d_in, const int* in_sizes, int n_in,
                              void* d_out, int out_size) {
    const float* x     = (const float*)d_in[0];
    const void*  ei    = d_in[1];
    const void*  batch = d_in[2];
    const float* W1    = (const float*)d_in[3];
    const float* b1    = (const float*)d_in[4];
    const float* W2    = (const float*)d_in[5];
    const float* b2    = (const float*)d_in[6];
    float* out = (float*)d_out;

    int n = in_sizes[0] / DNF;   // 50000
    int e = in_sizes[1] / 2;     // 800000

    int tb = 256;
    int gn = (n + tb - 1) / tb;
    int ge = (e + tb - 1) / tb;

    detect_kernel<<<1, 32>>>((const int*)ei);

    // CSR build (shared by both layers)
    init_deg_kernel<<<gn, tb>>>(n);
    count_deg_kernel<<<ge, tb>>>(ei, e);
    dinv_kernel<<<gn, tb>>>(n);
    scan_kernel<<<1, 512>>>(n);
    copy_pos_kernel<<<gn, tb>>>(n);
    fill_kernel<<<ge, tb>>>(ei, e);

    int gemm_blocks = (n + 63) / 64;
    int agg_blocks  = (n + 7) / 8;   // 8 warps/block, one warp per node

    // Layer 1
    gemm_scale_kernel<<<gemm_blocks, 256>>>(x, W1, 1, n);
    aggregate_kernel<<<agg_blocks, 256>>>(b1, n);
    // Layer 2
    gemm_scale_kernel<<<gemm_blocks, 256>>>(x, W2, 0, n);
    aggregate_kernel<<<agg_blocks, 256>>>(b2, n);

    // Pool
    pool_kernel<<<NGRAPH, 160>>>(batch, out, n);
}